// round 2
// baseline (speedup 1.0000x reference)
#include <cuda_runtime.h>
#include <math.h>
#include <stdint.h>

#define HEAD_DIM   128
#define NUM_HEADS  32
#define KVH        8
#define G          4
#define BLOCK_SZ   16
#define D_KV       (KVH * HEAD_DIM)
#define MAX_BPS    128
#define MAX_CTX    2048
#define NUM_BLOCKS 4096
#define NSLOTS     (NUM_BLOCKS * BLOCK_SZ)
#define BATCH      32
#define CHUNK      256
#define NCHUNK     (MAX_CTX / CHUNK)
#define NBLK       (CHUNK / BLOCK_SZ)       // 16 cache blocks per CTA
#define SCALE_F    0.08838834764831845f

__device__ int   g_inv[NSLOTS];
__device__ float g_pm  [BATCH * KVH * NCHUNK * G];
__device__ float g_pl  [BATCH * KVH * NCHUNK * G];
__device__ float g_pacc[BATCH * KVH * NCHUNK * G * HEAD_DIM];

// ---------------------------------------------------------------------------
// Kernel 1: inverse slot map, slots cached in smem.
// ---------------------------------------------------------------------------
__global__ void inv_kernel(const int* __restrict__ slot, int B) {
    __shared__ int sl[64];
    if (threadIdx.x < B) sl[threadIdx.x] = slot[threadIdx.x];
    __syncthreads();
    int i = blockIdx.x * blockDim.x + threadIdx.x;
    if (i >= NSLOTS) return;
    int r = -1;
    for (int j = 0; j < B; j++)
        if (sl[j] == i) r = j;
    g_inv[i] = r;
}

__device__ __forceinline__ float dot4(float4 a, float4 b) {
    return a.x * b.x + a.y * b.y + a.z * b.z + a.w * b.w;
}

// ---------------------------------------------------------------------------
// Kernel 2: split-KV flash-decode, software-pipelined.
// grid = (NCHUNK, KVH, B), 128 threads.
// Score mapping: t = tid>>3 (token), part = tid&7 (16-dim slice).
// V stage mapping: warp w stores rows w, w+4, w+8, w+12.
// Accumulate mapping: thread = output dim.
// ---------------------------------------------------------------------------
__global__ void __launch_bounds__(128) attn_kernel(
    const float* __restrict__ q,
    const float* __restrict__ knew,
    const float* __restrict__ vnew,
    const float* __restrict__ kc,
    const float* __restrict__ vc,
    const int*   __restrict__ bt,
    const int*   __restrict__ ctx_lens,
    const int*   __restrict__ slot, int B)
{
    const int b     = blockIdx.z;
    const int h     = blockIdx.y;
    const int chunk = blockIdx.x;

    const int ctx   = ctx_lens[b];
    const int start = chunk * CHUNK;
    if (start >= ctx) return;
    const int end = (start + CHUNK < ctx) ? (start + CHUNK) : ctx;
    const int nb  = (end - start + BLOCK_SZ - 1) / BLOCK_SZ;

    const int tid  = threadIdx.x;
    const int t    = tid >> 3;
    const int part = tid & 7;
    const int w    = tid >> 5;
    const int lane = tid & 31;

    __shared__ float v_sh[2][BLOCK_SZ][HEAD_DIM];   // 16 KB double-buffered
    __shared__ float s_sh[G][BLOCK_SZ];
    __shared__ float p_sh[G][BLOCK_SZ];
    __shared__ float st_m[G], st_l[G], alpha_sh[G];
    __shared__ int   ph_sh[NBLK];
    __shared__ int   ov_sh[NBLK];
    __shared__ int   sl_sh[64];

    // ---- prologue: phys ids, slots, override flags ----
    if (tid < B)  sl_sh[tid] = slot[tid];
    if (tid < nb) ph_sh[tid] = bt[b * MAX_BPS + (start >> 4) + tid];
    if (tid < G)  { st_m[tid] = -3.0e38f; st_l[tid] = 0.0f; }
    __syncthreads();
    if (tid < nb) {
        const int p0 = ph_sh[tid] * BLOCK_SZ;
        int f = 0;
        for (int j = 0; j < B; j++) {
            const int s = sl_sh[j];
            f |= (s >= p0) & (s < p0 + BLOCK_SZ);
        }
        ov_sh[tid] = f;
    }
    __syncthreads();

    // q slice in registers: 4 heads x 16 dims
    float4 qr[G][4];
    #pragma unroll
    for (int g = 0; g < G; g++) {
        const float4* qp = (const float4*)(q + ((size_t)b * NUM_HEADS + (size_t)(h * G + g)) * HEAD_DIM + part * 16);
        #pragma unroll
        for (int l = 0; l < 4; l++) qr[g][l] = qp[l];
    }

    float acc[G] = {0.f, 0.f, 0.f, 0.f};

    float4 kr[4];   // K row slice for current block
    float4 vr[4];   // V rows (4 per thread) for current block

    // ---- prefetch block 0 into registers ----
    {
        const int phys = ph_sh[0];
        const int ovr  = ov_sh[0];
        // K
        {
            const int flat = phys * BLOCK_SZ + t;
            const float* krow;
            if (ovr) {
                const int r = g_inv[flat];
                krow = (r >= 0) ? (knew + ((size_t)r * KVH + h) * HEAD_DIM)
                                : (kc + (size_t)flat * D_KV + (size_t)h * HEAD_DIM);
            } else {
                krow = kc + (size_t)flat * D_KV + (size_t)h * HEAD_DIM;
            }
            const float4* kp = (const float4*)(krow + part * 16);
            kr[0] = kp[0]; kr[1] = kp[1]; kr[2] = kp[2]; kr[3] = kp[3];
        }
        // V
        #pragma unroll
        for (int l = 0; l < 4; l++) {
            const int tv   = w + l * 4;
            const int flat = phys * BLOCK_SZ + tv;
            const float* vrow;
            if (ovr) {
                const int r = g_inv[flat];
                vrow = (r >= 0) ? (vnew + ((size_t)r * KVH + h) * HEAD_DIM)
                                : (vc + (size_t)flat * D_KV + (size_t)h * HEAD_DIM);
            } else {
                vrow = vc + (size_t)flat * D_KV + (size_t)h * HEAD_DIM;
            }
            vr[l] = ((const float4*)vrow)[lane];
        }
    }

    int buf = 0;
    for (int jj = 0; jj < nb; jj++) {
        // ---- stage V regs into smem (buffer `buf`) ----
        #pragma unroll
        for (int l = 0; l < 4; l++)
            ((float4*)&v_sh[buf][w + l * 4][0])[lane] = vr[l];

        // ---- scores from K regs ----
        {
            float s[G];
            #pragma unroll
            for (int g = 0; g < G; g++)
                s[g] = dot4(qr[g][0], kr[0]) + dot4(qr[g][1], kr[1])
                     + dot4(qr[g][2], kr[2]) + dot4(qr[g][3], kr[3]);
            #pragma unroll
            for (int g = 0; g < G; g++) {
                s[g] += __shfl_xor_sync(0xffffffffu, s[g], 1);
                s[g] += __shfl_xor_sync(0xffffffffu, s[g], 2);
                s[g] += __shfl_xor_sync(0xffffffffu, s[g], 4);
            }
            const int tok = start + jj * BLOCK_SZ + t;
            if (part == 0) {
                #pragma unroll
                for (int g = 0; g < G; g++)
                    s_sh[g][t] = (tok < ctx) ? s[g] * SCALE_F : -1.0e30f;
            }
        }

        // ---- prefetch block jj+1 into registers (overlaps softmax+accum) ----
        if (jj + 1 < nb) {
            const int phys = ph_sh[jj + 1];
            const int ovr  = ov_sh[jj + 1];
            {
                const int flat = phys * BLOCK_SZ + t;
                const float* krow;
                if (ovr) {
                    const int r = g_inv[flat];
                    krow = (r >= 0) ? (knew + ((size_t)r * KVH + h) * HEAD_DIM)
                                    : (kc + (size_t)flat * D_KV + (size_t)h * HEAD_DIM);
                } else {
                    krow = kc + (size_t)flat * D_KV + (size_t)h * HEAD_DIM;
                }
                const float4* kp = (const float4*)(krow + part * 16);
                kr[0] = kp[0]; kr[1] = kp[1]; kr[2] = kp[2]; kr[3] = kp[3];
            }
            #pragma unroll
            for (int l = 0; l < 4; l++) {
                const int tv   = w + l * 4;
                const int flat = phys * BLOCK_SZ + tv;
                const float* vrow;
                if (ovr) {
                    const int r = g_inv[flat];
                    vrow = (r >= 0) ? (vnew + ((size_t)r * KVH + h) * HEAD_DIM)
                                    : (vc + (size_t)flat * D_KV + (size_t)h * HEAD_DIM);
                } else {
                    vrow = vc + (size_t)flat * D_KV + (size_t)h * HEAD_DIM;
                }
                vr[l] = ((const float4*)vrow)[lane];
            }
        }

        __syncthreads();   // s_sh + v_sh[buf] visible

        // ---- parallel softmax: 64 threads = 4 heads x 16 tokens ----
        if (tid < 64) {
            const int g  = tid >> 4;
            const int tt = tid & 15;
            const float sv = s_sh[g][tt];
            float mb = sv;
            #pragma unroll
            for (int d = 8; d >= 1; d >>= 1)
                mb = fmaxf(mb, __shfl_xor_sync(0xffffffffu, mb, d, 16));
            const float m_old = st_m[g];
            const float m_new = fmaxf(m_old, mb);
            const float p = __expf(sv - m_new);
            p_sh[g][tt] = p;
            float sum = p;
            #pragma unroll
            for (int d = 8; d >= 1; d >>= 1)
                sum += __shfl_xor_sync(0xffffffffu, sum, d, 16);
            if (tt == 0) {
                const float alpha = __expf(m_old - m_new);
                st_l[g] = st_l[g] * alpha + sum;
                st_m[g] = m_new;
                alpha_sh[g] = alpha;
            }
        }
        __syncthreads();   // p_sh + alpha_sh visible

        // ---- accumulate: thread owns dim d = tid ----
        {
            acc[0] *= alpha_sh[0]; acc[1] *= alpha_sh[1];
            acc[2] *= alpha_sh[2]; acc[3] *= alpha_sh[3];
            #pragma unroll
            for (int tt = 0; tt < BLOCK_SZ; tt++) {
                const float vv = v_sh[buf][tt][tid];
                acc[0] += p_sh[0][tt] * vv;
                acc[1] += p_sh[1][tt] * vv;
                acc[2] += p_sh[2][tt] * vv;
                acc[3] += p_sh[3][tt] * vv;
            }
        }
        buf ^= 1;
    }

    // ---- write chunk partials ----
    const int base = ((b * KVH + h) * NCHUNK + chunk) * G;
    #pragma unroll
    for (int g = 0; g < G; g++)
        g_pacc[(size_t)(base + g) * HEAD_DIM + tid] = acc[g];
    __syncthreads();
    if (tid < G) {
        g_pm[base + tid] = st_m[tid];
        g_pl[base + tid] = st_l[tid];
    }
}

// ---------------------------------------------------------------------------
// Kernel 3: combine chunk partials (log-sum-exp).
// ---------------------------------------------------------------------------
__global__ void __launch_bounds__(128) reduce_kernel(
    float* __restrict__ out, const int* __restrict__ ctx_lens)
{
    const int bh = blockIdx.x;
    const int b  = bh / KVH;
    const int h  = bh % KVH;
    const int d  = threadIdx.x;

    const int ctx = ctx_lens[b];
    const int nv  = (ctx + CHUNK - 1) / CHUNK;

    #pragma unroll
    for (int g = 0; g < G; g++) {
        const int base0 = (b * KVH + h) * NCHUNK * G + g;
        float M = -3.0e38f;
        for (int c = 0; c < nv; c++) M = fmaxf(M, g_pm[base0 + c * G]);
        float L = 0.0f, o = 0.0f;
        for (int c = 0; c < nv; c++) {
            float wgt = __expf(g_pm[base0 + c * G] - M);
            L += wgt * g_pl[base0 + c * G];
            o += wgt * g_pacc[(size_t)(base0 + c * G) * HEAD_DIM + d];
        }
        out[((size_t)b * NUM_HEADS + (size_t)(h * G + g)) * HEAD_DIM + d] = o / L;
    }
}

extern "C" void kernel_launch(void* const* d_in, const int* in_sizes, int n_in,
                              void* d_out, int out_size) {
    const float* q    = (const float*)d_in[0];
    const float* k    = (const float*)d_in[1];
    const float* v    = (const float*)d_in[2];
    const float* kc   = (const float*)d_in[3];
    const float* vc   = (const float*)d_in[4];
    const int*   slot = (const int*)d_in[5];
    const int*   bt   = (const int*)d_in[6];
    const int*   ctx  = (const int*)d_in[7];

    const int B = in_sizes[5];

    inv_kernel<<<(NSLOTS + 255) / 256, 256>>>(slot, B);

    dim3 grid(NCHUNK, KVH, BATCH);
    attn_kernel<<<grid, 128>>>(q, k, v, kc, vc, bt, ctx, slot, B);

    reduce_kernel<<<BATCH * KVH, HEAD_DIM>>>((float*)d_out, ctx);
}

// round 3
// speedup vs baseline: 1.0038x; 1.0038x over previous
#include <cuda_runtime.h>
#include <math.h>
#include <stdint.h>

#define HEAD_DIM   128
#define NUM_HEADS  32
#define KVH        8
#define G          4
#define BLOCK_SZ   16
#define D_KV       (KVH * HEAD_DIM)
#define MAX_BPS    128
#define MAX_CTX    2048
#define NUM_BLOCKS 4096
#define NSLOTS     (NUM_BLOCKS * BLOCK_SZ)
#define BATCH      32
#define CHUNK      256
#define NCHUNK     (MAX_CTX / CHUNK)
#define NBLK       (CHUNK / BLOCK_SZ)       // 16 cache blocks per CTA
#define SCALE_F    0.08838834764831845f

__device__ int   g_inv[NSLOTS];
__device__ float g_pm  [BATCH * KVH * NCHUNK * G];
__device__ float g_pl  [BATCH * KVH * NCHUNK * G];
__device__ float g_pacc[BATCH * KVH * NCHUNK * G * HEAD_DIM];

// ---------------------------------------------------------------------------
// Kernel 1: inverse slot map, slots cached in smem.
// ---------------------------------------------------------------------------
__global__ void inv_kernel(const int* __restrict__ slot, int B) {
    __shared__ int sl[64];
    if (threadIdx.x < B) sl[threadIdx.x] = slot[threadIdx.x];
    __syncthreads();
    int i = blockIdx.x * blockDim.x + threadIdx.x;
    if (i >= NSLOTS) return;
    int r = -1;
    for (int j = 0; j < B; j++)
        if (sl[j] == i) r = j;
    g_inv[i] = r;
}

__device__ __forceinline__ float dot4(float4 a, float4 b) {
    return a.x * b.x + a.y * b.y + a.z * b.z + a.w * b.w;
}

// ---------------------------------------------------------------------------
// Kernel 2: split-KV flash-decode, software-pipelined.
// grid = (NCHUNK, KVH, B), 128 threads.
// Score mapping: t = tid>>3 (token), part = tid&7 (16-dim slice).
// V stage mapping: warp w stores rows w, w+4, w+8, w+12.
// Accumulate mapping: thread = output dim.
// ---------------------------------------------------------------------------
__global__ void __launch_bounds__(128) attn_kernel(
    const float* __restrict__ q,
    const float* __restrict__ knew,
    const float* __restrict__ vnew,
    const float* __restrict__ kc,
    const float* __restrict__ vc,
    const int*   __restrict__ bt,
    const int*   __restrict__ ctx_lens,
    const int*   __restrict__ slot, int B)
{
    const int b     = blockIdx.z;
    const int h     = blockIdx.y;
    const int chunk = blockIdx.x;

    const int ctx   = ctx_lens[b];
    const int start = chunk * CHUNK;
    if (start >= ctx) return;
    const int end = (start + CHUNK < ctx) ? (start + CHUNK) : ctx;
    const int nb  = (end - start + BLOCK_SZ - 1) / BLOCK_SZ;

    const int tid  = threadIdx.x;
    const int t    = tid >> 3;
    const int part = tid & 7;
    const int w    = tid >> 5;
    const int lane = tid & 31;

    __shared__ float v_sh[2][BLOCK_SZ][HEAD_DIM];   // 16 KB double-buffered
    __shared__ float s_sh[G][BLOCK_SZ];
    __shared__ float p_sh[G][BLOCK_SZ];
    __shared__ float st_m[G], st_l[G], alpha_sh[G];
    __shared__ int   ph_sh[NBLK];
    __shared__ int   ov_sh[NBLK];
    __shared__ int   sl_sh[64];

    // ---- prologue: phys ids, slots, override flags ----
    if (tid < B)  sl_sh[tid] = slot[tid];
    if (tid < nb) ph_sh[tid] = bt[b * MAX_BPS + (start >> 4) + tid];
    if (tid < G)  { st_m[tid] = -3.0e38f; st_l[tid] = 0.0f; }
    __syncthreads();
    if (tid < nb) {
        const int p0 = ph_sh[tid] * BLOCK_SZ;
        int f = 0;
        for (int j = 0; j < B; j++) {
            const int s = sl_sh[j];
            f |= (s >= p0) & (s < p0 + BLOCK_SZ);
        }
        ov_sh[tid] = f;
    }
    __syncthreads();

    // q slice in registers: 4 heads x 16 dims
    float4 qr[G][4];
    #pragma unroll
    for (int g = 0; g < G; g++) {
        const float4* qp = (const float4*)(q + ((size_t)b * NUM_HEADS + (size_t)(h * G + g)) * HEAD_DIM + part * 16);
        #pragma unroll
        for (int l = 0; l < 4; l++) qr[g][l] = qp[l];
    }

    float acc[G] = {0.f, 0.f, 0.f, 0.f};

    float4 kr[4];   // K row slice for current block
    float4 vr[4];   // V rows (4 per thread) for current block

    // ---- prefetch block 0 into registers ----
    {
        const int phys = ph_sh[0];
        const int ovr  = ov_sh[0];
        // K
        {
            const int flat = phys * BLOCK_SZ + t;
            const float* krow;
            if (ovr) {
                const int r = g_inv[flat];
                krow = (r >= 0) ? (knew + ((size_t)r * KVH + h) * HEAD_DIM)
                                : (kc + (size_t)flat * D_KV + (size_t)h * HEAD_DIM);
            } else {
                krow = kc + (size_t)flat * D_KV + (size_t)h * HEAD_DIM;
            }
            const float4* kp = (const float4*)(krow + part * 16);
            kr[0] = kp[0]; kr[1] = kp[1]; kr[2] = kp[2]; kr[3] = kp[3];
        }
        // V
        #pragma unroll
        for (int l = 0; l < 4; l++) {
            const int tv   = w + l * 4;
            const int flat = phys * BLOCK_SZ + tv;
            const float* vrow;
            if (ovr) {
                const int r = g_inv[flat];
                vrow = (r >= 0) ? (vnew + ((size_t)r * KVH + h) * HEAD_DIM)
                                : (vc + (size_t)flat * D_KV + (size_t)h * HEAD_DIM);
            } else {
                vrow = vc + (size_t)flat * D_KV + (size_t)h * HEAD_DIM;
            }
            vr[l] = ((const float4*)vrow)[lane];
        }
    }

    int buf = 0;
    for (int jj = 0; jj < nb; jj++) {
        // ---- stage V regs into smem (buffer `buf`) ----
        #pragma unroll
        for (int l = 0; l < 4; l++)
            ((float4*)&v_sh[buf][w + l * 4][0])[lane] = vr[l];

        // ---- scores from K regs ----
        {
            float s[G];
            #pragma unroll
            for (int g = 0; g < G; g++)
                s[g] = dot4(qr[g][0], kr[0]) + dot4(qr[g][1], kr[1])
                     + dot4(qr[g][2], kr[2]) + dot4(qr[g][3], kr[3]);
            #pragma unroll
            for (int g = 0; g < G; g++) {
                s[g] += __shfl_xor_sync(0xffffffffu, s[g], 1);
                s[g] += __shfl_xor_sync(0xffffffffu, s[g], 2);
                s[g] += __shfl_xor_sync(0xffffffffu, s[g], 4);
            }
            const int tok = start + jj * BLOCK_SZ + t;
            if (part == 0) {
                #pragma unroll
                for (int g = 0; g < G; g++)
                    s_sh[g][t] = (tok < ctx) ? s[g] * SCALE_F : -1.0e30f;
            }
        }

        // ---- prefetch block jj+1 into registers (overlaps softmax+accum) ----
        if (jj + 1 < nb) {
            const int phys = ph_sh[jj + 1];
            const int ovr  = ov_sh[jj + 1];
            {
                const int flat = phys * BLOCK_SZ + t;
                const float* krow;
                if (ovr) {
                    const int r = g_inv[flat];
                    krow = (r >= 0) ? (knew + ((size_t)r * KVH + h) * HEAD_DIM)
                                    : (kc + (size_t)flat * D_KV + (size_t)h * HEAD_DIM);
                } else {
                    krow = kc + (size_t)flat * D_KV + (size_t)h * HEAD_DIM;
                }
                const float4* kp = (const float4*)(krow + part * 16);
                kr[0] = kp[0]; kr[1] = kp[1]; kr[2] = kp[2]; kr[3] = kp[3];
            }
            #pragma unroll
            for (int l = 0; l < 4; l++) {
                const int tv   = w + l * 4;
                const int flat = phys * BLOCK_SZ + tv;
                const float* vrow;
                if (ovr) {
                    const int r = g_inv[flat];
                    vrow = (r >= 0) ? (vnew + ((size_t)r * KVH + h) * HEAD_DIM)
                                    : (vc + (size_t)flat * D_KV + (size_t)h * HEAD_DIM);
                } else {
                    vrow = vc + (size_t)flat * D_KV + (size_t)h * HEAD_DIM;
                }
                vr[l] = ((const float4*)vrow)[lane];
            }
        }

        __syncthreads();   // s_sh + v_sh[buf] visible

        // ---- parallel softmax: 64 threads = 4 heads x 16 tokens ----
        if (tid < 64) {
            const int g  = tid >> 4;
            const int tt = tid & 15;
            const float sv = s_sh[g][tt];
            float mb = sv;
            #pragma unroll
            for (int d = 8; d >= 1; d >>= 1)
                mb = fmaxf(mb, __shfl_xor_sync(0xffffffffu, mb, d, 16));
            const float m_old = st_m[g];
            const float m_new = fmaxf(m_old, mb);
            const float p = __expf(sv - m_new);
            p_sh[g][tt] = p;
            float sum = p;
            #pragma unroll
            for (int d = 8; d >= 1; d >>= 1)
                sum += __shfl_xor_sync(0xffffffffu, sum, d, 16);
            if (tt == 0) {
                const float alpha = __expf(m_old - m_new);
                st_l[g] = st_l[g] * alpha + sum;
                st_m[g] = m_new;
                alpha_sh[g] = alpha;
            }
        }
        __syncthreads();   // p_sh + alpha_sh visible

        // ---- accumulate: thread owns dim d = tid ----
        {
            acc[0] *= alpha_sh[0]; acc[1] *= alpha_sh[1];
            acc[2] *= alpha_sh[2]; acc[3] *= alpha_sh[3];
            #pragma unroll
            for (int tt = 0; tt < BLOCK_SZ; tt++) {
                const float vv = v_sh[buf][tt][tid];
                acc[0] += p_sh[0][tt] * vv;
                acc[1] += p_sh[1][tt] * vv;
                acc[2] += p_sh[2][tt] * vv;
                acc[3] += p_sh[3][tt] * vv;
            }
        }
        buf ^= 1;
    }

    // ---- write chunk partials ----
    const int base = ((b * KVH + h) * NCHUNK + chunk) * G;
    #pragma unroll
    for (int g = 0; g < G; g++)
        g_pacc[(size_t)(base + g) * HEAD_DIM + tid] = acc[g];
    __syncthreads();
    if (tid < G) {
        g_pm[base + tid] = st_m[tid];
        g_pl[base + tid] = st_l[tid];
    }
}

// ---------------------------------------------------------------------------
// Kernel 3: combine chunk partials (log-sum-exp).
// ---------------------------------------------------------------------------
__global__ void __launch_bounds__(128) reduce_kernel(
    float* __restrict__ out, const int* __restrict__ ctx_lens)
{
    const int bh = blockIdx.x;
    const int b  = bh / KVH;
    const int h  = bh % KVH;
    const int d  = threadIdx.x;

    const int ctx = ctx_lens[b];
    const int nv  = (ctx + CHUNK - 1) / CHUNK;

    #pragma unroll
    for (int g = 0; g < G; g++) {
        const int base0 = (b * KVH + h) * NCHUNK * G + g;
        float M = -3.0e38f;
        for (int c = 0; c < nv; c++) M = fmaxf(M, g_pm[base0 + c * G]);
        float L = 0.0f, o = 0.0f;
        for (int c = 0; c < nv; c++) {
            float wgt = __expf(g_pm[base0 + c * G] - M);
            L += wgt * g_pl[base0 + c * G];
            o += wgt * g_pacc[(size_t)(base0 + c * G) * HEAD_DIM + d];
        }
        out[((size_t)b * NUM_HEADS + (size_t)(h * G + g)) * HEAD_DIM + d] = o / L;
    }
}

extern "C" void kernel_launch(void* const* d_in, const int* in_sizes, int n_in,
                              void* d_out, int out_size) {
    const float* q    = (const float*)d_in[0];
    const float* k    = (const float*)d_in[1];
    const float* v    = (const float*)d_in[2];
    const float* kc   = (const float*)d_in[3];
    const float* vc   = (const float*)d_in[4];
    const int*   slot = (const int*)d_in[5];
    const int*   bt   = (const int*)d_in[6];
    const int*   ctx  = (const int*)d_in[7];

    const int B = in_sizes[5];

    inv_kernel<<<(NSLOTS + 255) / 256, 256>>>(slot, B);

    dim3 grid(NCHUNK, KVH, BATCH);
    attn_kernel<<<grid, 128>>>(q, k, v, kc, vc, bt, ctx, slot, B);

    reduce_kernel<<<BATCH * KVH, HEAD_DIM>>>((float*)d_out, ctx);
}

// round 7
// speedup vs baseline: 1.3680x; 1.3628x over previous
#include <cuda_runtime.h>
#include <math.h>
#include <stdint.h>

#define HEAD_DIM   128
#define NUM_HEADS  32
#define KVH        8
#define G          4
#define BLOCK_SZ   16
#define D_KV       (KVH * HEAD_DIM)
#define MAX_BPS    128
#define MAX_CTX    2048
#define BATCH      32
#define CHUNK      256
#define NCHUNK     (MAX_CTX / CHUNK)
#define NBLK       (CHUNK / BLOCK_SZ)
#define SCALE_F    0.08838834764831845f

__device__ float g_pm  [BATCH * KVH * NCHUNK * G];
__device__ float g_pl  [BATCH * KVH * NCHUNK * G];
__device__ float g_pacc[BATCH * KVH * NCHUNK * G * HEAD_DIM];

__device__ __forceinline__ float dot4(float4 a, float4 b) {
    return a.x * b.x + a.y * b.y + a.z * b.z + a.w * b.w;
}

__device__ __forceinline__ void cp16(uint32_t dst, const void* src) {
    asm volatile("cp.async.cg.shared.global [%0], [%1], 16;\n" :: "r"(dst), "l"(src));
}
__device__ __forceinline__ void cp_commit() {
    asm volatile("cp.async.commit_group;\n" ::);
}
template <int N>
__device__ __forceinline__ void cp_wait() {
    asm volatile("cp.async.wait_group %0;\n" :: "n"(N));
}

// Issue one 16-token cache block (K + V, 8KB each) into smem buffers.
// row = tid>>3 (token row this thread copies), sl = tid&7 (16B segment lane).
__device__ __forceinline__ void issue_block(
    int phys, int ovr, int row, int sl,
    uint32_t kdst, uint32_t vdst,
    const float* __restrict__ kc, const float* __restrict__ vc,
    const float* __restrict__ knew, const float* __restrict__ vnew,
    const int* sl_sh, int B, int h)
{
    const int flat = phys * BLOCK_SZ + row;
    const float* krow;
    const float* vrow;
    if (ovr) {
        int r = -1;
        #pragma unroll 4
        for (int j = 0; j < B; j++)
            if (sl_sh[j] == flat) r = j;
        if (r >= 0) {
            krow = knew + ((size_t)r * KVH + h) * HEAD_DIM;
            vrow = vnew + ((size_t)r * KVH + h) * HEAD_DIM;
        } else {
            krow = kc + (size_t)flat * D_KV + (size_t)h * HEAD_DIM;
            vrow = vc + (size_t)flat * D_KV + (size_t)h * HEAD_DIM;
        }
    } else {
        krow = kc + (size_t)flat * D_KV + (size_t)h * HEAD_DIM;
        vrow = vc + (size_t)flat * D_KV + (size_t)h * HEAD_DIM;
    }
    const uint32_t kb = kdst + row * 512 + sl * 16;
    const uint32_t vb = vdst + row * 512 + sl * 16;
    const char* kp = (const char*)krow + sl * 16;
    const char* vp = (const char*)vrow + sl * 16;
    #pragma unroll
    for (int i = 0; i < 4; i++) {
        cp16(kb + i * 128, kp + i * 128);
        cp16(vb + i * 128, vp + i * 128);
    }
}

// ---------------------------------------------------------------------------
// Split-KV flash-decode. grid = (NCHUNK, KVH, B), 128 threads.
// Scores: part = tid&15 owns dims {4p..4p+4, 64+4p..64+4p+4}; trow = tid>>4
// handles tokens trow and trow+8. Accumulate: thread = output dim.
// ---------------------------------------------------------------------------
__global__ void __launch_bounds__(128, 6) attn_kernel(
    const float* __restrict__ q,
    const float* __restrict__ knew,
    const float* __restrict__ vnew,
    const float* __restrict__ kc,
    const float* __restrict__ vc,
    const int*   __restrict__ bt,
    const int*   __restrict__ ctx_lens,
    const int*   __restrict__ slot, int B)
{
    const int b     = blockIdx.z;
    const int h     = blockIdx.y;
    const int chunk = blockIdx.x;

    const int ctx   = ctx_lens[b];
    const int start = chunk * CHUNK;
    if (start >= ctx) return;
    const int end = (start + CHUNK < ctx) ? (start + CHUNK) : ctx;
    const int nb  = (end - start + BLOCK_SZ - 1) / BLOCK_SZ;

    const int tid  = threadIdx.x;
    const int part = tid & 15;
    const int trow = tid >> 4;
    const int row  = tid >> 3;   // cp.async row
    const int sl   = tid & 7;    // cp.async 16B segment

    __shared__ float k_sh[2][BLOCK_SZ][HEAD_DIM];   // 16 KB
    __shared__ float v_sh[2][BLOCK_SZ][HEAD_DIM];   // 16 KB
    __shared__ float s_sh[G][BLOCK_SZ];
    __shared__ float p_sh[G][BLOCK_SZ];
    __shared__ float st_m[G], st_l[G], alpha_sh[G];
    __shared__ int   ph_sh[NBLK];
    __shared__ int   ov_sh[NBLK];
    __shared__ int   sl_sh[64];

    // ---- prologue ----
    if (tid < B)  sl_sh[tid] = slot[tid];
    if (tid < nb) ph_sh[tid] = bt[b * MAX_BPS + (start >> 4) + tid];
    if (tid < G)  { st_m[tid] = -3.0e38f; st_l[tid] = 0.0f; }
    __syncthreads();
    if (tid < nb) {
        const int p0 = ph_sh[tid] * BLOCK_SZ;
        int f = 0;
        for (int j = 0; j < B; j++) {
            const int s = sl_sh[j];
            f |= (s >= p0) & (s < p0 + BLOCK_SZ);
        }
        ov_sh[tid] = f;
    }
    __syncthreads();

    const uint32_t kbase = (uint32_t)__cvta_generic_to_shared(&k_sh[0][0][0]);
    const uint32_t vbase = (uint32_t)__cvta_generic_to_shared(&v_sh[0][0][0]);

    // q: 4 heads x 8 dims per thread (32 regs)
    float4 qr[G][2];
    #pragma unroll
    for (int g = 0; g < G; g++) {
        const float4* qp = (const float4*)(q + ((size_t)b * NUM_HEADS + (size_t)(h * G + g)) * HEAD_DIM);
        qr[g][0] = qp[part];
        qr[g][1] = qp[16 + part];
    }

    float acc[G] = {0.f, 0.f, 0.f, 0.f};

    // ---- prefetch depth 2 ----
    issue_block(ph_sh[0], ov_sh[0], row, sl, kbase, vbase,
                kc, vc, knew, vnew, sl_sh, B, h);
    cp_commit();
    if (nb > 1) {
        issue_block(ph_sh[1], ov_sh[1], row, sl, kbase + 8192, vbase + 8192,
                    kc, vc, knew, vnew, sl_sh, B, h);
        cp_commit();
    }

    const int hsel = part & 3;

    int buf = 0;
    for (int jj = 0; jj < nb; jj++) {
        if (jj == nb - 1) cp_wait<0>(); else cp_wait<1>();
        __syncthreads();   // block jj resident + everyone past wait

        // ---- scores from k_sh[buf] ----
        {
            const float4* ks4 = (const float4*)&k_sh[buf][0][0];
            float xs[2];
            #pragma unroll
            for (int tp = 0; tp < 2; tp++) {
                const int tok = trow + tp * 8;
                const float4 k0 = ks4[tok * 32 + part];
                const float4 k1 = ks4[tok * 32 + 16 + part];
                float s0 = dot4(qr[0][0], k0) + dot4(qr[0][1], k1);
                float s1 = dot4(qr[1][0], k0) + dot4(qr[1][1], k1);
                float s2 = dot4(qr[2][0], k0) + dot4(qr[2][1], k1);
                float s3 = dot4(qr[3][0], k0) + dot4(qr[3][1], k1);
                // quad reduce (lanes with same part>>2)
                s0 += __shfl_xor_sync(0xffffffffu, s0, 1, 16);
                s1 += __shfl_xor_sync(0xffffffffu, s1, 1, 16);
                s2 += __shfl_xor_sync(0xffffffffu, s2, 1, 16);
                s3 += __shfl_xor_sync(0xffffffffu, s3, 1, 16);
                s0 += __shfl_xor_sync(0xffffffffu, s0, 2, 16);
                s1 += __shfl_xor_sync(0xffffffffu, s1, 2, 16);
                s2 += __shfl_xor_sync(0xffffffffu, s2, 2, 16);
                s3 += __shfl_xor_sync(0xffffffffu, s3, 2, 16);
                // transpose: lane carries head (part&3), reduce across quads
                float x = (hsel == 0) ? s0 : (hsel == 1) ? s1 : (hsel == 2) ? s2 : s3;
                x += __shfl_xor_sync(0xffffffffu, x, 4, 16);
                x += __shfl_xor_sync(0xffffffffu, x, 8, 16);
                xs[tp] = x;
            }
            if (part < 4) {
                const int t0 = start + jj * BLOCK_SZ;
                s_sh[part][trow]     = (t0 + trow     < ctx) ? xs[0] * SCALE_F : -1.0e30f;
                s_sh[part][trow + 8] = (t0 + trow + 8 < ctx) ? xs[1] * SCALE_F : -1.0e30f;
            }
        }
        __syncthreads();   // s_sh ready

        // ---- parallel softmax: 64 threads = 4 heads x 16 tokens ----
        if (tid < 64) {
            const int g  = tid >> 4;
            const int tt = tid & 15;
            const float sv = s_sh[g][tt];
            float mb = sv;
            #pragma unroll
            for (int d = 8; d >= 1; d >>= 1)
                mb = fmaxf(mb, __shfl_xor_sync(0xffffffffu, mb, d, 16));
            const float m_old = st_m[g];
            const float m_new = fmaxf(m_old, mb);
            const float p = __expf(sv - m_new);
            p_sh[g][tt] = p;
            float sum = p;
            #pragma unroll
            for (int d = 8; d >= 1; d >>= 1)
                sum += __shfl_xor_sync(0xffffffffu, sum, d, 16);
            if (tt == 0) {
                const float alpha = __expf(m_old - m_new);
                st_l[g] = st_l[g] * alpha + sum;
                st_m[g] = m_new;
                alpha_sh[g] = alpha;
            }
        }
        __syncthreads();   // p_sh + alpha_sh ready

        // ---- accumulate: thread owns dim d = tid ----
        {
            acc[0] *= alpha_sh[0]; acc[1] *= alpha_sh[1];
            acc[2] *= alpha_sh[2]; acc[3] *= alpha_sh[3];
            #pragma unroll
            for (int tt = 0; tt < BLOCK_SZ; tt++) {
                const float vv = v_sh[buf][tt][tid];
                acc[0] += p_sh[0][tt] * vv;
                acc[1] += p_sh[1][tt] * vv;
                acc[2] += p_sh[2][tt] * vv;
                acc[3] += p_sh[3][tt] * vv;
            }
        }
        __syncthreads();   // done reading buf; safe to refill

        if (jj + 2 < nb) {
            issue_block(ph_sh[jj + 2], ov_sh[jj + 2], row, sl,
                        kbase + buf * 8192, vbase + buf * 8192,
                        kc, vc, knew, vnew, sl_sh, B, h);
            cp_commit();
        }
        buf ^= 1;
    }

    // ---- write chunk partials ----
    const int base = ((b * KVH + h) * NCHUNK + chunk) * G;
    #pragma unroll
    for (int g = 0; g < G; g++)
        g_pacc[(size_t)(base + g) * HEAD_DIM + tid] = acc[g];
    if (tid < G) {
        g_pm[base + tid] = st_m[tid];
        g_pl[base + tid] = st_l[tid];
    }
}

// ---------------------------------------------------------------------------
// Combine chunk partials (log-sum-exp).
// ---------------------------------------------------------------------------
__global__ void __launch_bounds__(128) reduce_kernel(
    float* __restrict__ out, const int* __restrict__ ctx_lens)
{
    const int bh = blockIdx.x;
    const int b  = bh / KVH;
    const int h  = bh % KVH;
    const int d  = threadIdx.x;

    const int ctx = ctx_lens[b];
    const int nv  = (ctx + CHUNK - 1) / CHUNK;

    #pragma unroll
    for (int g = 0; g < G; g++) {
        const int base0 = (b * KVH + h) * NCHUNK * G + g;
        float M = -3.0e38f;
        for (int c = 0; c < nv; c++) M = fmaxf(M, g_pm[base0 + c * G]);
        float L = 0.0f, o = 0.0f;
        for (int c = 0; c < nv; c++) {
            float wgt = __expf(g_pm[base0 + c * G] - M);
            L += wgt * g_pl[base0 + c * G];
            o += wgt * g_pacc[(size_t)(base0 + c * G) * HEAD_DIM + d];
        }
        out[((size_t)b * NUM_HEADS + (size_t)(h * G + g)) * HEAD_DIM + d] = o / L;
    }
}

extern "C" void kernel_launch(void* const* d_in, const int* in_sizes, int n_in,
                              void* d_out, int out_size) {
    const float* q    = (const float*)d_in[0];
    const float* k    = (const float*)d_in[1];
    const float* v    = (const float*)d_in[2];
    const float* kc   = (const float*)d_in[3];
    const float* vc   = (const float*)d_in[4];
    const int*   slot = (const int*)d_in[5];
    const int*   bt   = (const int*)d_in[6];
    const int*   ctx  = (const int*)d_in[7];

    const int B = in_sizes[5];

    dim3 grid(NCHUNK, KVH, BATCH);
    attn_kernel<<<grid, 128>>>(q, k, v, kc, vc, bt, ctx, slot, B);

    reduce_kernel<<<BATCH * KVH, HEAD_DIM>>>((float*)d_out, ctx);
}

// round 8
// speedup vs baseline: 1.4846x; 1.0852x over previous
#include <cuda_runtime.h>
#include <math.h>
#include <stdint.h>

#define HEAD_DIM   128
#define NUM_HEADS  32
#define KVH        8
#define G          4
#define BLOCK_SZ   16
#define D_KV       (KVH * HEAD_DIM)
#define MAX_BPS    128
#define MAX_CTX    2048
#define BATCH      32
#define CHUNK      256
#define NCHUNK     (MAX_CTX / CHUNK)
#define NBLK       (CHUNK / BLOCK_SZ)
#define SCALE_F    0.08838834764831845f

__device__ float g_pm  [BATCH * KVH * NCHUNK * G];
__device__ float g_pl  [BATCH * KVH * NCHUNK * G];
__device__ float g_pacc[BATCH * KVH * NCHUNK * G * HEAD_DIM];

__device__ __forceinline__ float dot4(float4 a, float4 b) {
    return a.x * b.x + a.y * b.y + a.z * b.z + a.w * b.w;
}

__device__ __forceinline__ void cp16(uint32_t dst, const void* src) {
    asm volatile("cp.async.cg.shared.global [%0], [%1], 16;\n" :: "r"(dst), "l"(src));
}
__device__ __forceinline__ void cp_commit() {
    asm volatile("cp.async.commit_group;\n" ::);
}
template <int N>
__device__ __forceinline__ void cp_wait() {
    asm volatile("cp.async.wait_group %0;\n" :: "n"(N));
}

// Issue one 16-token cache block (K + V, 8KB each) into smem buffers.
__device__ __forceinline__ void issue_block(
    int phys, int ovr, int row, int sl,
    uint32_t kdst, uint32_t vdst,
    const float* __restrict__ kc, const float* __restrict__ vc,
    const float* __restrict__ knew, const float* __restrict__ vnew,
    const int* sl_sh, int B, int h)
{
    const int flat = phys * BLOCK_SZ + row;
    const float* krow;
    const float* vrow;
    if (ovr) {
        int r = -1;
        #pragma unroll 4
        for (int j = 0; j < B; j++)
            if (sl_sh[j] == flat) r = j;
        if (r >= 0) {
            krow = knew + ((size_t)r * KVH + h) * HEAD_DIM;
            vrow = vnew + ((size_t)r * KVH + h) * HEAD_DIM;
        } else {
            krow = kc + (size_t)flat * D_KV + (size_t)h * HEAD_DIM;
            vrow = vc + (size_t)flat * D_KV + (size_t)h * HEAD_DIM;
        }
    } else {
        krow = kc + (size_t)flat * D_KV + (size_t)h * HEAD_DIM;
        vrow = vc + (size_t)flat * D_KV + (size_t)h * HEAD_DIM;
    }
    const uint32_t kb = kdst + row * 512 + sl * 16;
    const uint32_t vb = vdst + row * 512 + sl * 16;
    const char* kp = (const char*)krow + sl * 16;
    const char* vp = (const char*)vrow + sl * 16;
    #pragma unroll
    for (int i = 0; i < 4; i++) {
        cp16(kb + i * 128, kp + i * 128);
        cp16(vb + i * 128, vp + i * 128);
    }
}

// ---------------------------------------------------------------------------
// Split-KV flash-decode. grid = (NCHUNK, KVH, B), 128 threads.
// ---------------------------------------------------------------------------
__global__ void __launch_bounds__(128, 6) attn_kernel(
    const float* __restrict__ q,
    const float* __restrict__ knew,
    const float* __restrict__ vnew,
    const float* __restrict__ kc,
    const float* __restrict__ vc,
    const int*   __restrict__ bt,
    const int*   __restrict__ ctx_lens,
    const int*   __restrict__ slot, int B,
    float* __restrict__ out)
{
    const int b     = blockIdx.z;
    const int h     = blockIdx.y;
    const int chunk = blockIdx.x;

    const int ctx   = ctx_lens[b];
    const int start = chunk * CHUNK;
    if (start >= ctx) return;
    const int end = (start + CHUNK < ctx) ? (start + CHUNK) : ctx;
    const int nb  = (end - start + BLOCK_SZ - 1) / BLOCK_SZ;

    const int tid  = threadIdx.x;
    const int part = tid & 15;
    const int trow = tid >> 4;
    const int row  = tid >> 3;   // cp.async row
    const int sl   = tid & 7;    // cp.async 16B segment

    __shared__ float k_sh[2][BLOCK_SZ][HEAD_DIM];   // 16 KB
    __shared__ float v_sh[2][BLOCK_SZ][HEAD_DIM];   // 16 KB
    __shared__ float s_sh[G][BLOCK_SZ];
    __shared__ float p_sh[G][BLOCK_SZ];
    __shared__ float st_m[G], st_l[G], alpha_sh[G];
    __shared__ int   ph_sh[NBLK];
    __shared__ int   ov_sh[NBLK];
    __shared__ int   sl_sh[64];

    // ---- prologue ----
    if (tid < B)  sl_sh[tid] = slot[tid];
    if (tid < nb) ph_sh[tid] = bt[b * MAX_BPS + (start >> 4) + tid];
    if (tid < G)  { st_m[tid] = -3.0e38f; st_l[tid] = 0.0f; }
    __syncthreads();
    if (tid < nb) {
        const int p0 = ph_sh[tid] * BLOCK_SZ;
        int f = 0;
        for (int j = 0; j < B; j++) {
            const int s = sl_sh[j];
            f |= (s >= p0) & (s < p0 + BLOCK_SZ);
        }
        ov_sh[tid] = f;
    }
    __syncthreads();

    const uint32_t kbase = (uint32_t)__cvta_generic_to_shared(&k_sh[0][0][0]);
    const uint32_t vbase = (uint32_t)__cvta_generic_to_shared(&v_sh[0][0][0]);

    // q: 4 heads x 8 dims per thread (32 regs)
    float4 qr[G][2];
    #pragma unroll
    for (int g = 0; g < G; g++) {
        const float4* qp = (const float4*)(q + ((size_t)b * NUM_HEADS + (size_t)(h * G + g)) * HEAD_DIM);
        qr[g][0] = qp[part];
        qr[g][1] = qp[16 + part];
    }

    float acc[G] = {0.f, 0.f, 0.f, 0.f};

    // ---- prefetch depth 2 ----
    issue_block(ph_sh[0], ov_sh[0], row, sl, kbase, vbase,
                kc, vc, knew, vnew, sl_sh, B, h);
    cp_commit();
    if (nb > 1) {
        issue_block(ph_sh[1], ov_sh[1], row, sl, kbase + 8192, vbase + 8192,
                    kc, vc, knew, vnew, sl_sh, B, h);
        cp_commit();
    }

    const int hsel = part & 3;

    int buf = 0;
    for (int jj = 0; jj < nb; jj++) {
        if (jj == nb - 1) cp_wait<0>(); else cp_wait<1>();
        __syncthreads();

        // ---- scores from k_sh[buf] ----
        {
            const float4* ks4 = (const float4*)&k_sh[buf][0][0];
            float xs[2];
            #pragma unroll
            for (int tp = 0; tp < 2; tp++) {
                const int tok = trow + tp * 8;
                const float4 k0 = ks4[tok * 32 + part];
                const float4 k1 = ks4[tok * 32 + 16 + part];
                float s0 = dot4(qr[0][0], k0) + dot4(qr[0][1], k1);
                float s1 = dot4(qr[1][0], k0) + dot4(qr[1][1], k1);
                float s2 = dot4(qr[2][0], k0) + dot4(qr[2][1], k1);
                float s3 = dot4(qr[3][0], k0) + dot4(qr[3][1], k1);
                s0 += __shfl_xor_sync(0xffffffffu, s0, 1, 16);
                s1 += __shfl_xor_sync(0xffffffffu, s1, 1, 16);
                s2 += __shfl_xor_sync(0xffffffffu, s2, 1, 16);
                s3 += __shfl_xor_sync(0xffffffffu, s3, 1, 16);
                s0 += __shfl_xor_sync(0xffffffffu, s0, 2, 16);
                s1 += __shfl_xor_sync(0xffffffffu, s1, 2, 16);
                s2 += __shfl_xor_sync(0xffffffffu, s2, 2, 16);
                s3 += __shfl_xor_sync(0xffffffffu, s3, 2, 16);
                float x = (hsel == 0) ? s0 : (hsel == 1) ? s1 : (hsel == 2) ? s2 : s3;
                x += __shfl_xor_sync(0xffffffffu, x, 4, 16);
                x += __shfl_xor_sync(0xffffffffu, x, 8, 16);
                xs[tp] = x;
            }
            if (part < 4) {
                const int t0 = start + jj * BLOCK_SZ;
                s_sh[part][trow]     = (t0 + trow     < ctx) ? xs[0] * SCALE_F : -1.0e30f;
                s_sh[part][trow + 8] = (t0 + trow + 8 < ctx) ? xs[1] * SCALE_F : -1.0e30f;
            }
        }
        __syncthreads();

        // ---- parallel softmax: 64 threads = 4 heads x 16 tokens ----
        if (tid < 64) {
            const int g  = tid >> 4;
            const int tt = tid & 15;
            const float sv = s_sh[g][tt];
            float mb = sv;
            #pragma unroll
            for (int d = 8; d >= 1; d >>= 1)
                mb = fmaxf(mb, __shfl_xor_sync(0xffffffffu, mb, d, 16));
            const float m_old = st_m[g];
            const float m_new = fmaxf(m_old, mb);
            const float p = __expf(sv - m_new);
            p_sh[g][tt] = p;
            float sum = p;
            #pragma unroll
            for (int d = 8; d >= 1; d >>= 1)
                sum += __shfl_xor_sync(0xffffffffu, sum, d, 16);
            if (tt == 0) {
                const float alpha = __expf(m_old - m_new);
                st_l[g] = st_l[g] * alpha + sum;
                st_m[g] = m_new;
                alpha_sh[g] = alpha;
            }
        }
        __syncthreads();

        // ---- accumulate: thread owns dim d = tid ----
        {
            acc[0] *= alpha_sh[0]; acc[1] *= alpha_sh[1];
            acc[2] *= alpha_sh[2]; acc[3] *= alpha_sh[3];
            #pragma unroll
            for (int tt = 0; tt < BLOCK_SZ; tt++) {
                const float vv = v_sh[buf][tt][tid];
                acc[0] += p_sh[0][tt] * vv;
                acc[1] += p_sh[1][tt] * vv;
                acc[2] += p_sh[2][tt] * vv;
                acc[3] += p_sh[3][tt] * vv;
            }
        }
        __syncthreads();

        if (jj + 2 < nb) {
            issue_block(ph_sh[jj + 2], ov_sh[jj + 2], row, sl,
                        kbase + buf * 8192, vbase + buf * 8192,
                        kc, vc, knew, vnew, sl_sh, B, h);
            cp_commit();
        }
        buf ^= 1;
    }

    if (ctx <= CHUNK) {
        // single-chunk fast path: write final output directly
        #pragma unroll
        for (int g = 0; g < G; g++)
            out[((size_t)b * NUM_HEADS + (size_t)(h * G + g)) * HEAD_DIM + tid]
                = acc[g] / st_l[g];
        return;
    }

    // ---- write chunk partials ----
    const int base = ((b * KVH + h) * NCHUNK + chunk) * G;
    #pragma unroll
    for (int g = 0; g < G; g++)
        g_pacc[(size_t)(base + g) * HEAD_DIM + tid] = acc[g];
    if (tid < G) {
        g_pm[base + tid] = st_m[tid];
        g_pl[base + tid] = st_l[tid];
    }
}

// ---------------------------------------------------------------------------
// Combine chunk partials (log-sum-exp), batched independent loads.
// grid = B*KVH*G, block = 128 (thread = dim).
// ---------------------------------------------------------------------------
__global__ void __launch_bounds__(128) reduce_kernel(
    float* __restrict__ out, const int* __restrict__ ctx_lens)
{
    const int idx = blockIdx.x;
    const int g   = idx & (G - 1);
    const int bh  = idx >> 2;
    const int b   = bh / KVH;
    const int h   = bh % KVH;
    const int d   = threadIdx.x;

    const int ctx = ctx_lens[b];
    const int nv  = (ctx + CHUNK - 1) / CHUNK;
    if (nv == 1) return;   // attn kernel wrote output directly

    const int base0 = (b * KVH + h) * NCHUNK * G + g;

    // Phase 1: all pm + pl loads issued together (independent, MLP=16)
    float pm[NCHUNK], pl[NCHUNK];
    #pragma unroll
    for (int c = 0; c < NCHUNK; c++) {
        pm[c] = (c < nv) ? __ldg(&g_pm[base0 + c * G]) : -3.0e38f;
        pl[c] = (c < nv) ? __ldg(&g_pl[base0 + c * G]) : 0.0f;
    }

    float M = -3.0e38f;
    #pragma unroll
    for (int c = 0; c < NCHUNK; c++) M = fmaxf(M, pm[c]);

    float wgt[NCHUNK];
    float L = 0.0f;
    #pragma unroll
    for (int c = 0; c < NCHUNK; c++) {
        wgt[c] = (c < nv) ? __expf(pm[c] - M) : 0.0f;
        L += wgt[c] * pl[c];
    }

    // Phase 2: all pacc loads issued together (independent, MLP=8)
    float pa[NCHUNK];
    #pragma unroll
    for (int c = 0; c < NCHUNK; c++)
        pa[c] = (c < nv) ? __ldg(&g_pacc[(size_t)(base0 + c * G) * HEAD_DIM + d]) : 0.0f;

    float o = 0.0f;
    #pragma unroll
    for (int c = 0; c < NCHUNK; c++) o += wgt[c] * pa[c];

    out[((size_t)b * NUM_HEADS + (size_t)(h * G + g)) * HEAD_DIM + d] = o / L;
}

extern "C" void kernel_launch(void* const* d_in, const int* in_sizes, int n_in,
                              void* d_out, int out_size) {
    const float* q    = (const float*)d_in[0];
    const float* k    = (const float*)d_in[1];
    const float* v    = (const float*)d_in[2];
    const float* kc   = (const float*)d_in[3];
    const float* vc   = (const float*)d_in[4];
    const int*   slot = (const int*)d_in[5];
    const int*   bt   = (const int*)d_in[6];
    const int*   ctx  = (const int*)d_in[7];

    const int B = in_sizes[5];

    dim3 grid(NCHUNK, KVH, BATCH);
    attn_kernel<<<grid, 128>>>(q, k, v, kc, vc, bt, ctx, slot, B, (float*)d_out);

    reduce_kernel<<<BATCH * KVH * G, HEAD_DIM>>>((float*)d_out, ctx);
}